// round 1
// baseline (speedup 1.0000x reference)
#include <cuda_runtime.h>
#include <math.h>

#define TT 256
#define BB 32
#define INS 1024
#define HH 1024
#define G4 (4*HH)

// Scratch (no cudaMalloc allowed)
__device__ float g_gates[(size_t)TT*BB*G4];  // 128MB, reused per layer
__device__ float g_y1[(size_t)TT*BB*HH];     // layer-0 outputs
__device__ float g_c[BB*HH];                 // running cell state

// ---------------------------------------------------------------------------
// Input GEMM: C[M,4096] = A[M,K] * W[4096,K]^T + (bW[n]+bR[n])
// BM=BN=128, BK=8, 256 threads, 8x8 per thread, float4 loads.
// ---------------------------------------------------------------------------
__global__ void gemm_xw(const float* __restrict__ A, const float* __restrict__ W,
                        const float* __restrict__ bW, const float* __restrict__ bR,
                        float* __restrict__ C, int M, int K)
{
    __shared__ float As[8][128];
    __shared__ float Bs[8][128];
    const int bm = blockIdx.y * 128;
    const int bn = blockIdx.x * 128;
    const int tid = threadIdx.x;

    const int l_row  = tid >> 1;          // 0..127
    const int l_col4 = (tid & 1) * 4;     // 0 or 4

    const int tm = (tid >> 4) * 8;        // 0..120
    const int tn = (tid & 15) * 8;        // 0..120

    float acc[8][8];
    #pragma unroll
    for (int i = 0; i < 8; i++)
        #pragma unroll
        for (int j = 0; j < 8; j++) acc[i][j] = 0.f;

    for (int k0 = 0; k0 < K; k0 += 8) {
        float4 av = *reinterpret_cast<const float4*>(A + (size_t)(bm + l_row) * K + k0 + l_col4);
        float4 wv = *reinterpret_cast<const float4*>(W + (size_t)(bn + l_row) * K + k0 + l_col4);
        As[l_col4+0][l_row] = av.x; As[l_col4+1][l_row] = av.y;
        As[l_col4+2][l_row] = av.z; As[l_col4+3][l_row] = av.w;
        Bs[l_col4+0][l_row] = wv.x; Bs[l_col4+1][l_row] = wv.y;
        Bs[l_col4+2][l_row] = wv.z; Bs[l_col4+3][l_row] = wv.w;
        __syncthreads();

        #pragma unroll
        for (int kk = 0; kk < 8; kk++) {
            float ra[8], rb[8];
            float4 a0 = *reinterpret_cast<const float4*>(&As[kk][tm]);
            float4 a1 = *reinterpret_cast<const float4*>(&As[kk][tm+4]);
            float4 b0 = *reinterpret_cast<const float4*>(&Bs[kk][tn]);
            float4 b1 = *reinterpret_cast<const float4*>(&Bs[kk][tn+4]);
            ra[0]=a0.x; ra[1]=a0.y; ra[2]=a0.z; ra[3]=a0.w;
            ra[4]=a1.x; ra[5]=a1.y; ra[6]=a1.z; ra[7]=a1.w;
            rb[0]=b0.x; rb[1]=b0.y; rb[2]=b0.z; rb[3]=b0.w;
            rb[4]=b1.x; rb[5]=b1.y; rb[6]=b1.z; rb[7]=b1.w;
            #pragma unroll
            for (int i = 0; i < 8; i++)
                #pragma unroll
                for (int j = 0; j < 8; j++)
                    acc[i][j] += ra[i] * rb[j];
        }
        __syncthreads();
    }

    float bias[8];
    #pragma unroll
    for (int j = 0; j < 8; j++) bias[j] = bW[bn+tn+j] + bR[bn+tn+j];

    #pragma unroll
    for (int i = 0; i < 8; i++) {
        float* crow = C + (size_t)(bm + tm + i) * G4 + bn + tn;
        #pragma unroll
        for (int j = 0; j < 8; j++) crow[j] = acc[i][j] + bias[j];
    }
}

// ---------------------------------------------------------------------------
// Fused recurrent step: for a block's 8 h-columns, compute all 4 gate columns
// g = gates_x[t] + y_prev @ R^T, then the cell update, in one kernel.
// grid = H/8 = 128 blocks, 256 threads (= 4 K-slices x 64 threads, 4x4 tiles).
// ---------------------------------------------------------------------------
#define KC 16
__global__ void lstm_step(const float* __restrict__ gates_t,  // [B,4H] at time t
                          const float* __restrict__ Rm,       // [4H,H]
                          const float* __restrict__ y_prev,   // [B,H]
                          float* __restrict__ c_state,        // [B,H]
                          float* __restrict__ y_out)          // [B,H]
{
    const int hbase = blockIdx.x * 8;
    const int tid = threadIdx.x;
    const int s   = tid >> 6;              // k-slice 0..3 (k in [s*256,(s+1)*256))
    const int t64 = tid & 63;
    const int tc  = (t64 & 7) * 4;         // c0 in [0,32): col c -> gate c>>3, h hbase+(c&7)
    const int tb  = (t64 >> 3) * 4;        // b0 in [0,32)

    __shared__ float ys[4][KC][36];        // [slice][k][b]
    __shared__ float rs[4][KC][36];        // [slice][k][c]
    __shared__ float accs[4][32][33];      // per-slice partial outputs [s][b][c]

    float acc[4][4];
    #pragma unroll
    for (int i = 0; i < 4; i++)
        #pragma unroll
        for (int j = 0; j < 4; j++) acc[i][j] = 0.f;

    const int kslice0 = s * 256;

    for (int kc = 0; kc < 256; kc += KC) {
        const int kb = kslice0 + kc;
        // load y chunk: 128 float4 slots per slice, 64 threads -> 2 each
        #pragma unroll
        for (int it = 0; it < 2; it++) {
            int lin = t64 + it * 64;       // 0..127
            int b   = lin >> 2;            // 0..31
            int kk4 = (lin & 3) * 4;       // 0,4,8,12
            float4 v = *reinterpret_cast<const float4*>(y_prev + (size_t)b * HH + kb + kk4);
            ys[s][kk4+0][b] = v.x; ys[s][kk4+1][b] = v.y;
            ys[s][kk4+2][b] = v.z; ys[s][kk4+3][b] = v.w;
        }
        // load R chunk
        #pragma unroll
        for (int it = 0; it < 2; it++) {
            int lin = t64 + it * 64;
            int c   = lin >> 2;            // 0..31
            int kk4 = (lin & 3) * 4;
            int n   = (c >> 3) * HH + hbase + (c & 7);
            float4 v = *reinterpret_cast<const float4*>(Rm + (size_t)n * HH + kb + kk4);
            rs[s][kk4+0][c] = v.x; rs[s][kk4+1][c] = v.y;
            rs[s][kk4+2][c] = v.z; rs[s][kk4+3][c] = v.w;
        }
        __syncthreads();

        #pragma unroll
        for (int kk = 0; kk < KC; kk++) {
            float4 yv = *reinterpret_cast<const float4*>(&ys[s][kk][tb]);
            float4 rv = *reinterpret_cast<const float4*>(&rs[s][kk][tc]);
            float ry[4] = {yv.x, yv.y, yv.z, yv.w};
            float rr[4] = {rv.x, rv.y, rv.z, rv.w};
            #pragma unroll
            for (int i = 0; i < 4; i++)
                #pragma unroll
                for (int j = 0; j < 4; j++)
                    acc[i][j] += ry[i] * rr[j];
        }
        __syncthreads();
    }

    #pragma unroll
    for (int i = 0; i < 4; i++)
        #pragma unroll
        for (int j = 0; j < 4; j++)
            accs[s][tb+i][tc+j] = acc[i][j];
    __syncthreads();

    // Pointwise cell update: 256 threads -> 32 b x 8 h cells
    {
        const int b = tid >> 3;
        const int j = tid & 7;
        const int h = hbase + j;
        const float* grow = gates_t + (size_t)b * G4;
        float vi = grow[0*HH + h];
        float vf = grow[1*HH + h];
        float vg = grow[2*HH + h];
        float vo = grow[3*HH + h];
        #pragma unroll
        for (int ss = 0; ss < 4; ss++) {
            vi += accs[ss][b][j];
            vf += accs[ss][b][8 + j];
            vg += accs[ss][b][16 + j];
            vo += accs[ss][b][24 + j];
        }
        float ig = 1.f / (1.f + __expf(-vi));
        float fg = 1.f / (1.f + __expf(-vf));
        float gg = tanhf(vg);
        float og = 1.f / (1.f + __expf(-vo));
        float cold = c_state[b * HH + h];
        float cnew = fg * cold + ig * gg;
        float ynew = og * tanhf(cnew);
        c_state[b * HH + h] = cnew;
        y_out[b * HH + h] = ynew;
    }
}

// ---------------------------------------------------------------------------
extern "C" void kernel_launch(void* const* d_in, const int* in_sizes, int n_in,
                              void* d_out, int out_size)
{
    const float* x   = (const float*)d_in[0];
    const float* h0  = (const float*)d_in[1];
    const float* c0  = (const float*)d_in[2];
    const float* W0  = (const float*)d_in[3];
    const float* R0  = (const float*)d_in[4];
    const float* bW0 = (const float*)d_in[5];
    const float* bR0 = (const float*)d_in[6];
    const float* W1  = (const float*)d_in[7];
    const float* R1  = (const float*)d_in[8];
    const float* bW1 = (const float*)d_in[9];
    const float* bR1 = (const float*)d_in[10];

    float* y2 = (float*)d_out;                      // [T,B,H]
    float* hn = y2 + (size_t)TT * BB * HH;          // [2,B,H]
    float* cn = hn + 2 * BB * HH;                   // [2,B,H]

    float *gates, *y1, *cbuf;
    cudaGetSymbolAddress((void**)&gates, g_gates);
    cudaGetSymbolAddress((void**)&y1,    g_y1);
    cudaGetSymbolAddress((void**)&cbuf,  g_c);

    const size_t bhBytes = (size_t)BB * HH * sizeof(float);
    dim3 ggrid(G4 / 128, (TT * BB) / 128);

    // ---- layer 0 ----
    gemm_xw<<<ggrid, 256>>>(x, W0, bW0, bR0, gates, TT * BB, INS);
    cudaMemcpyAsync(cbuf, c0, bhBytes, cudaMemcpyDeviceToDevice);
    for (int t = 0; t < TT; t++) {
        const float* yp = (t == 0) ? h0 : (y1 + (size_t)(t - 1) * BB * HH);
        lstm_step<<<HH / 8, 256>>>(gates + (size_t)t * BB * G4, R0, yp, cbuf,
                                   y1 + (size_t)t * BB * HH);
    }
    cudaMemcpyAsync(hn, y1 + (size_t)(TT - 1) * BB * HH, bhBytes, cudaMemcpyDeviceToDevice);
    cudaMemcpyAsync(cn, cbuf, bhBytes, cudaMemcpyDeviceToDevice);

    // ---- layer 1 ----
    gemm_xw<<<ggrid, 256>>>(y1, W1, bW1, bR1, gates, TT * BB, HH);
    cudaMemcpyAsync(cbuf, c0 + BB * HH, bhBytes, cudaMemcpyDeviceToDevice);
    for (int t = 0; t < TT; t++) {
        const float* yp = (t == 0) ? (h0 + BB * HH) : (y2 + (size_t)(t - 1) * BB * HH);
        lstm_step<<<HH / 8, 256>>>(gates + (size_t)t * BB * G4, R1, yp, cbuf,
                                   y2 + (size_t)t * BB * HH);
    }
    cudaMemcpyAsync(hn + BB * HH, y2 + (size_t)(TT - 1) * BB * HH, bhBytes, cudaMemcpyDeviceToDevice);
    cudaMemcpyAsync(cn + BB * HH, cbuf, bhBytes, cudaMemcpyDeviceToDevice);
}

// round 3
// speedup vs baseline: 1.7097x; 1.7097x over previous
#include <cuda_runtime.h>
#include <cuda_bf16.h>
#include <cstdint>
#include <math.h>

#define TT 256
#define BB 32
#define HH 1024
#define G4 4096
#define BH (BB*HH)
#define KC3 3072

// ---------------------------------------------------------------------------
// Static scratch (no cudaMalloc allowed)
// ---------------------------------------------------------------------------
__device__ __align__(16) float g_gates[(size_t)TT*BB*G4];          // 128 MB
__device__ __align__(16) float g_c[BH];
__device__ __align__(16) float g_yf[BH];
__device__ __align__(16) __nv_bfloat16 g_yh[2][BH];
__device__ __align__(16) __nv_bfloat16 g_yl[2][BH];
__device__ __align__(16) __nv_bfloat16 g_xcat[(size_t)TT*BB*KC3];  // [8192][3072]
__device__ __align__(16) __nv_bfloat16 g_ycat[(size_t)TT*BB*KC3];
__device__ __align__(16) __nv_bfloat16 g_w0cat[(size_t)G4*KC3];
__device__ __align__(16) __nv_bfloat16 g_w1cat[(size_t)G4*KC3];
__device__ __align__(16) __nv_bfloat16 g_R0h[(size_t)G4*HH];       // reordered
__device__ __align__(16) __nv_bfloat16 g_R0l[(size_t)G4*HH];
__device__ __align__(16) __nv_bfloat16 g_R1h[(size_t)G4*HH];
__device__ __align__(16) __nv_bfloat16 g_R1l[(size_t)G4*HH];

// ---------------------------------------------------------------------------
// PTX helpers (all sm_80/90 baseline legal — no 'a'-gated features)
// ---------------------------------------------------------------------------
__device__ __forceinline__ uint32_t s2u(const void* p) {
    uint32_t a;
    asm("{ .reg .u64 t; cvta.to.shared.u64 t, %1; cvt.u32.u64 %0, t; }" : "=r"(a) : "l"(p));
    return a;
}
__device__ __forceinline__ void cp16(uint32_t saddr, const void* g) {
    asm volatile("cp.async.cg.shared.global [%0], [%1], 16;" :: "r"(saddr), "l"(g));
}
#define CP_COMMIT() asm volatile("cp.async.commit_group;" ::: "memory")
#define CP_WAIT1()  asm volatile("cp.async.wait_group 1;" ::: "memory")

__device__ __forceinline__ void ldsm_x4(uint32_t* r, uint32_t addr) {
    asm volatile("ldmatrix.sync.aligned.m8n8.x4.shared.b16 {%0,%1,%2,%3}, [%4];"
        : "=r"(r[0]), "=r"(r[1]), "=r"(r[2]), "=r"(r[3]) : "r"(addr));
}
__device__ __forceinline__ void ldsm_x2(uint32_t* r, uint32_t addr) {
    asm volatile("ldmatrix.sync.aligned.m8n8.x2.shared.b16 {%0,%1}, [%2];"
        : "=r"(r[0]), "=r"(r[1]) : "r"(addr));
}
__device__ __forceinline__ void mma16816(float* d, const uint32_t* a, const uint32_t* b) {
    asm volatile("mma.sync.aligned.m16n8k16.row.col.f32.bf16.bf16.f32 "
        "{%0,%1,%2,%3}, {%4,%5,%6,%7}, {%8,%9}, {%0,%1,%2,%3};"
        : "+f"(d[0]), "+f"(d[1]), "+f"(d[2]), "+f"(d[3])
        : "r"(a[0]), "r"(a[1]), "r"(a[2]), "r"(a[3]), "r"(b[0]), "r"(b[1]));
}

// ---------------------------------------------------------------------------
// Conversions
// ---------------------------------------------------------------------------
// modeB=0 (A operand): [hi, hi, lo]; modeB=1 (B operand): [hi, lo, hi]
__global__ void split_cat(const float* __restrict__ src, __nv_bfloat16* __restrict__ dst,
                          size_t rows, int modeB) {
    size_t n = rows * HH;
    for (size_t i = (size_t)blockIdx.x * blockDim.x + threadIdx.x; i < n;
         i += (size_t)gridDim.x * blockDim.x) {
        size_t r = i >> 10; int k = (int)(i & 1023);
        float v = src[i];
        __nv_bfloat16 h = __float2bfloat16(v);
        __nv_bfloat16 l = __float2bfloat16(v - __bfloat162float(h));
        __nv_bfloat16* d = dst + r * KC3 + k;
        d[0] = h;
        d[1024] = modeB ? l : h;
        d[2048] = modeB ? h : l;
    }
}

// Reorder + split R: dst row d = blk*32 + gate*8 + hl ; src row = gate*1024 + blk*8 + hl
__global__ void split_R(const float* __restrict__ R, __nv_bfloat16* __restrict__ hi,
                        __nv_bfloat16* __restrict__ lo) {
    size_t n = (size_t)G4 * HH;
    for (size_t i = (size_t)blockIdx.x * blockDim.x + threadIdx.x; i < n;
         i += (size_t)gridDim.x * blockDim.x) {
        int d = (int)(i >> 10), k = (int)(i & 1023);
        int blk = d >> 5, gate = (d >> 3) & 3, hl = d & 7;
        int srow = gate * HH + blk * 8 + hl;
        float v = R[(size_t)srow * HH + k];
        __nv_bfloat16 h = __float2bfloat16(v);
        hi[i] = h;
        lo[i] = __float2bfloat16(v - __bfloat162float(h));
    }
}

__global__ void split_h0(const float* __restrict__ src, __nv_bfloat16* __restrict__ yh,
                         __nv_bfloat16* __restrict__ yl) {
    int i = blockIdx.x * blockDim.x + threadIdx.x;
    if (i < BH) {
        float v = src[i];
        __nv_bfloat16 h = __float2bfloat16(v);
        yh[i] = h;
        yl[i] = __float2bfloat16(v - __bfloat162float(h));
    }
}

// ---------------------------------------------------------------------------
// Big GEMM: out[M][4096] = A[M][3072] @ B[4096][3072]^T + bias
// BM=BN=128, BK=32, 256 threads (8 warps: wm=w&3 -> m32, wn=w>>2 -> n64)
// smem rows padded to 80B -> conflict-free ldmatrix without XOR swizzle.
// ---------------------------------------------------------------------------
#define GEMM_SMEM 40960

__device__ __forceinline__ void gemm_prefetch(uint32_t sb, int s,
    const __nv_bfloat16* __restrict__ A, const __nv_bfloat16* __restrict__ B,
    int m0, int n0, int k0, int tid)
{
    #pragma unroll
    for (int u = 0; u < 2; u++) {
        int unit = u * 256 + tid;
        int r = unit >> 2, c = unit & 3;
        cp16(sb + s * 20480 + r * 80 + c * 16, A + (size_t)(m0 + r) * KC3 + k0 + c * 8);
        cp16(sb + s * 20480 + 10240 + r * 80 + c * 16, B + (size_t)(n0 + r) * KC3 + k0 + c * 8);
    }
}

__global__ __launch_bounds__(256) void gemm_cat(
    const __nv_bfloat16* __restrict__ A, const __nv_bfloat16* __restrict__ B,
    const float* __restrict__ bW, const float* __restrict__ bR,
    float* __restrict__ out)
{
    extern __shared__ char smem[];
    const uint32_t sb = s2u(smem);
    const int tid = threadIdx.x, lane = tid & 31, w = tid >> 5;
    const int wm = w & 3, wn = w >> 2;
    const int m0 = blockIdx.y * 128, n0 = blockIdx.x * 128;

    float acc[2][8][4];
    #pragma unroll
    for (int i = 0; i < 2; i++)
        #pragma unroll
        for (int j = 0; j < 8; j++)
            #pragma unroll
            for (int q = 0; q < 4; q++) acc[i][j][q] = 0.f;

    gemm_prefetch(sb, 0, A, B, m0, n0, 0, tid); CP_COMMIT();
    gemm_prefetch(sb, 1, A, B, m0, n0, 32, tid); CP_COMMIT();

    for (int it = 0; it < 96; it++) {
        CP_WAIT1();
        __syncthreads();
        const int s = it & 1;
        const uint32_t ab = sb + s * 20480;
        const uint32_t bb = ab + 10240;
        #pragma unroll
        for (int kk = 0; kk < 2; kk++) {
            uint32_t af[2][4], bf[4][4];
            #pragma unroll
            for (int mh = 0; mh < 2; mh++) {
                int row = wm * 32 + mh * 16 + ((lane >> 3) & 1) * 8 + (lane & 7);
                int ch = kk * 2 + (lane >> 4);
                ldsm_x4(af[mh], ab + row * 80 + ch * 16);
            }
            #pragma unroll
            for (int p = 0; p < 4; p++) {
                int g = lane >> 3;
                int row = wn * 64 + p * 16 + (g >> 1) * 8 + (lane & 7);
                int ch = kk * 2 + (g & 1);
                ldsm_x4(bf[p], bb + row * 80 + ch * 16);
            }
            #pragma unroll
            for (int mh = 0; mh < 2; mh++)
                #pragma unroll
                for (int p = 0; p < 4; p++) {
                    mma16816(acc[mh][p * 2],     af[mh], &bf[p][0]);
                    mma16816(acc[mh][p * 2 + 1], af[mh], &bf[p][2]);
                }
        }
        __syncthreads();
        if (it + 2 < 96) gemm_prefetch(sb, s, A, B, m0, n0, (it + 2) * 32, tid);
        CP_COMMIT();
    }

    #pragma unroll
    for (int mh = 0; mh < 2; mh++)
        #pragma unroll
        for (int nj = 0; nj < 8; nj++) {
            int row = m0 + wm * 32 + mh * 16 + (lane >> 2);
            int col = n0 + wn * 64 + nj * 8 + 2 * (lane & 3);
            float b0 = bW[col] + bR[col];
            float b1 = bW[col + 1] + bR[col + 1];
            float2 v0 = make_float2(acc[mh][nj][0] + b0, acc[mh][nj][1] + b1);
            float2 v1 = make_float2(acc[mh][nj][2] + b0, acc[mh][nj][3] + b1);
            *reinterpret_cast<float2*>(out + (size_t)row * G4 + col) = v0;
            *reinterpret_cast<float2*>(out + (size_t)(row + 8) * G4 + col) = v1;
        }
}

// ---------------------------------------------------------------------------
// Recurrent step: 128 blocks x 128 threads. Block blk owns 32 reordered R rows
// (= 8 h x 4 gates). D[32b x 32col] = y[32][1024] @ Rblk[32][1024]^T, 3-term
// split bf16, fused cell update.
// smem: yh 64K | yl 64K | 2 x (Rh 8K + Rl 8K) | gs 32x33 f32
// ---------------------------------------------------------------------------
#define SYH 0
#define SYL 65536
#define SRB(s) (131072 + (s)*16384)
#define SGS 163840
#define STP_SMEM (163840 + 4224)

__device__ __forceinline__ void step_pref_r(uint32_t sb, int c, int s,
    const __nv_bfloat16* __restrict__ Rhb, const __nv_bfloat16* __restrict__ Rlb, int tid)
{
    #pragma unroll
    for (int u = 0; u < 8; u++) {
        int unit = u * 128 + tid;          // 0..1023
        int hs = unit >> 9, rem = unit & 511;
        int r = rem >> 4, cc = rem & 15;
        const __nv_bfloat16* src = (hs ? Rlb : Rhb) + (size_t)r * HH + c * 128 + cc * 8;
        uint32_t dst = sb + SRB(s) + hs * 8192 + r * 256 + ((cc ^ (r & 7)) * 16);
        cp16(dst, src);
    }
}

__global__ __launch_bounds__(128) void lstm_step_mma(
    const float* __restrict__ gates_t,
    const __nv_bfloat16* __restrict__ Rh, const __nv_bfloat16* __restrict__ Rl,
    const __nv_bfloat16* __restrict__ yhp, const __nv_bfloat16* __restrict__ ylp,
    __nv_bfloat16* __restrict__ yhn, __nv_bfloat16* __restrict__ yln,
    float* __restrict__ c_state, float* __restrict__ yf,
    __nv_bfloat16* __restrict__ ycat)
{
    extern __shared__ char smem[];
    const uint32_t sb = s2u(smem);
    const int tid = threadIdx.x, lane = tid & 31, w = tid >> 5;
    const int blk = blockIdx.x;

    // Early loads of pointwise operands (hidden under the K loop)
    float pre[2][5];
    #pragma unroll
    for (int q = 0; q < 2; q++) {
        int cell = tid + q * 128;
        int b = cell & 31, hl = cell >> 5;
        int h = blk * 8 + hl;
        const float* gx = gates_t + (size_t)b * G4;
        pre[q][0] = gx[h];
        pre[q][1] = gx[1024 + h];
        pre[q][2] = gx[2048 + h];
        pre[q][3] = gx[3072 + h];
        pre[q][4] = c_state[b * HH + h];
    }

    // y (hi+lo) -> smem, swizzled 16B chunks: chunk' = chunk ^ (row&7)
    #pragma unroll 4
    for (int u = 0; u < 64; u++) {
        int unit = u * 128 + tid;          // 0..8191
        int s = unit >> 12, rem = unit & 4095;
        int r = rem >> 7, c = rem & 127;
        const __nv_bfloat16* src = (s ? ylp : yhp) + (size_t)r * HH + c * 8;
        uint32_t dst = sb + (s ? SYL : SYH) + r * 2048 + ((c ^ (r & 7)) * 16);
        cp16(dst, src);
    }
    CP_COMMIT();

    const __nv_bfloat16* Rhb = Rh + (size_t)blk * 32 * HH;
    const __nv_bfloat16* Rlb = Rl + (size_t)blk * 32 * HH;
    step_pref_r(sb, 0, 0, Rhb, Rlb, tid); CP_COMMIT();
    step_pref_r(sb, 1, 1, Rhb, Rlb, tid); CP_COMMIT();

    float acc[2][4] = {{0.f,0.f,0.f,0.f},{0.f,0.f,0.f,0.f}};

    for (int c = 0; c < 8; c++) {
        CP_WAIT1();
        __syncthreads();
        const uint32_t rb = sb + SRB(c & 1);
        #pragma unroll
        for (int kk = 0; kk < 8; kk++) {
            uint32_t ah[2][4], al[2][4], bh[2], bl[2];
            #pragma unroll
            for (int mh = 0; mh < 2; mh++) {
                int row = mh * 16 + ((lane >> 3) & 1) * 8 + (lane & 7);
                int ch = (c * 16 + kk * 2 + (lane >> 4)) ^ (row & 7);
                ldsm_x4(ah[mh], sb + SYH + row * 2048 + ch * 16);
                ldsm_x4(al[mh], sb + SYL + row * 2048 + ch * 16);
            }
            {
                int r = w * 8 + (lane & 7);
                int ch = (kk * 2 + ((lane >> 3) & 1)) ^ (r & 7);
                ldsm_x2(bh, rb + r * 256 + ch * 16);
                ldsm_x2(bl, rb + 8192 + r * 256 + ch * 16);
            }
            #pragma unroll
            for (int mh = 0; mh < 2; mh++) {
                mma16816(acc[mh], ah[mh], bh);
                mma16816(acc[mh], ah[mh], bl);
                mma16816(acc[mh], al[mh], bh);
            }
        }
        __syncthreads();
        if (c + 2 < 8) step_pref_r(sb, c + 2, c & 1, Rhb, Rlb, tid);
        CP_COMMIT();
    }

    // Stage D (b rows x 32 cols) to smem for the gate exchange
    float* gs = reinterpret_cast<float*>(smem + SGS);
    #pragma unroll
    for (int mh = 0; mh < 2; mh++) {
        int b0 = mh * 16 + (lane >> 2);
        int cc = w * 8 + 2 * (lane & 3);
        gs[cc * 33 + b0] = acc[mh][0];
        gs[(cc + 1) * 33 + b0] = acc[mh][1];
        gs[cc * 33 + b0 + 8] = acc[mh][2];
        gs[(cc + 1) * 33 + b0 + 8] = acc[mh][3];
    }
    __syncthreads();

    #pragma unroll
    for (int q = 0; q < 2; q++) {
        int cell = tid + q * 128;
        int b = cell & 31, hl = cell >> 5;
        int h = blk * 8 + hl;
        float vi = pre[q][0] + gs[hl * 33 + b];
        float vf = pre[q][1] + gs[(8 + hl) * 33 + b];
        float vg = pre[q][2] + gs[(16 + hl) * 33 + b];
        float vo = pre[q][3] + gs[(24 + hl) * 33 + b];
        float ig = 1.f / (1.f + __expf(-vi));
        float fg = 1.f / (1.f + __expf(-vf));
        float gg = tanhf(vg);
        float og = 1.f / (1.f + __expf(-vo));
        float cn = fg * pre[q][4] + ig * gg;
        float yn = og * tanhf(cn);
        c_state[b * HH + h] = cn;
        yf[b * HH + h] = yn;
        __nv_bfloat16 yhv = __float2bfloat16(yn);
        __nv_bfloat16 ylv = __float2bfloat16(yn - __bfloat162float(yhv));
        yhn[b * HH + h] = yhv;
        yln[b * HH + h] = ylv;
        if (ycat) {
            __nv_bfloat16* d = ycat + (size_t)b * KC3 + h;
            d[0] = yhv; d[1024] = yhv; d[2048] = ylv;
        }
    }
}

// ---------------------------------------------------------------------------
extern "C" void kernel_launch(void* const* d_in, const int* in_sizes, int n_in,
                              void* d_out, int out_size)
{
    const float* x   = (const float*)d_in[0];
    const float* h0  = (const float*)d_in[1];
    const float* c0  = (const float*)d_in[2];
    const float* W0  = (const float*)d_in[3];
    const float* R0  = (const float*)d_in[4];
    const float* bW0 = (const float*)d_in[5];
    const float* bR0 = (const float*)d_in[6];
    const float* W1  = (const float*)d_in[7];
    const float* R1  = (const float*)d_in[8];
    const float* bW1 = (const float*)d_in[9];
    const float* bR1 = (const float*)d_in[10];

    float* y2 = (float*)d_out;
    float* hn = y2 + (size_t)TT * BH;
    float* cn = hn + 2 * BH;

    float *gates, *cbuf, *yf;
    __nv_bfloat16 *yh, *yl, *xcat, *ycat, *w0c, *w1c, *R0h, *R0l, *R1h, *R1l;
    cudaGetSymbolAddress((void**)&gates, g_gates);
    cudaGetSymbolAddress((void**)&cbuf,  g_c);
    cudaGetSymbolAddress((void**)&yf,    g_yf);
    cudaGetSymbolAddress((void**)&yh,    g_yh);
    cudaGetSymbolAddress((void**)&yl,    g_yl);
    cudaGetSymbolAddress((void**)&xcat,  g_xcat);
    cudaGetSymbolAddress((void**)&ycat,  g_ycat);
    cudaGetSymbolAddress((void**)&w0c,   g_w0cat);
    cudaGetSymbolAddress((void**)&w1c,   g_w1cat);
    cudaGetSymbolAddress((void**)&R0h,   g_R0h);
    cudaGetSymbolAddress((void**)&R0l,   g_R0l);
    cudaGetSymbolAddress((void**)&R1h,   g_R1h);
    cudaGetSymbolAddress((void**)&R1l,   g_R1l);

    cudaFuncSetAttribute(gemm_cat, cudaFuncAttributeMaxDynamicSharedMemorySize, GEMM_SMEM);
    cudaFuncSetAttribute(lstm_step_mma, cudaFuncAttributeMaxDynamicSharedMemorySize, STP_SMEM);

    const size_t bhBytes = (size_t)BH * sizeof(float);
    const dim3 ggrid(G4 / 128, (TT * BB) / 128);

    // ---- conversions ----
    split_cat<<<2048, 256>>>(x, xcat, (size_t)TT * BB, 0);
    split_cat<<<2048, 256>>>(W0, w0c, (size_t)G4, 1);
    split_cat<<<2048, 256>>>(W1, w1c, (size_t)G4, 1);
    split_R<<<2048, 256>>>(R0, R0h, R0l);
    split_R<<<2048, 256>>>(R1, R1h, R1l);

    // ---- layer 0 ----
    gemm_cat<<<ggrid, 256, GEMM_SMEM>>>(xcat, w0c, bW0, bR0, gates);
    split_h0<<<BH / 256, 256>>>(h0, yh, yl);                 // slot 0
    cudaMemcpyAsync(cbuf, c0, bhBytes, cudaMemcpyDeviceToDevice);
    for (int t = 0; t < TT; t++) {
        lstm_step_mma<<<128, 128, STP_SMEM>>>(
            gates + (size_t)t * BB * G4, R0h, R0l,
            yh + (size_t)(t & 1) * BH, yl + (size_t)(t & 1) * BH,
            yh + (size_t)((t + 1) & 1) * BH, yl + (size_t)((t + 1) & 1) * BH,
            cbuf, yf, ycat + (size_t)t * BB * KC3);
    }
    cudaMemcpyAsync(hn, yf, bhBytes, cudaMemcpyDeviceToDevice);
    cudaMemcpyAsync(cn, cbuf, bhBytes, cudaMemcpyDeviceToDevice);

    // ---- layer 1 ----
    gemm_cat<<<ggrid, 256, GEMM_SMEM>>>(ycat, w1c, bW1, bR1, gates);
    split_h0<<<BH / 256, 256>>>(h0 + BH, yh, yl);            // slot 0
    cudaMemcpyAsync(cbuf, c0 + BH, bhBytes, cudaMemcpyDeviceToDevice);
    for (int t = 0; t < TT; t++) {
        lstm_step_mma<<<128, 128, STP_SMEM>>>(
            gates + (size_t)t * BB * G4, R1h, R1l,
            yh + (size_t)(t & 1) * BH, yl + (size_t)(t & 1) * BH,
            yh + (size_t)((t + 1) & 1) * BH, yl + (size_t)((t + 1) & 1) * BH,
            cbuf, y2 + (size_t)t * BH, (__nv_bfloat16*)nullptr);
    }
    cudaMemcpyAsync(hn + BH, y2 + (size_t)(TT - 1) * BH, bhBytes, cudaMemcpyDeviceToDevice);
    cudaMemcpyAsync(cn + BH, cbuf, bhBytes, cudaMemcpyDeviceToDevice);
}

// round 4
// speedup vs baseline: 1.7390x; 1.0171x over previous
#include <cuda_runtime.h>
#include <cuda_bf16.h>
#include <cstdint>
#include <math.h>

#define TT 256
#define BB 32
#define HH 1024
#define G4 4096
#define BH (BB*HH)
#define KC3 3072

// ---------------------------------------------------------------------------
// Static scratch (no cudaMalloc allowed)
// ---------------------------------------------------------------------------
__device__ __align__(16) float g_gates[(size_t)TT*BB*G4];          // 128 MB
__device__ __align__(16) float g_yf[BH];
__device__ __align__(16) __nv_bfloat16 g_ybh[2][BH];               // y hi double buffer
__device__ __align__(16) __nv_bfloat16 g_ybl[2][BH];               // y lo double buffer
__device__ __align__(16) __nv_bfloat16 g_xcat[(size_t)TT*BB*KC3];  // [8192][3072]
__device__ __align__(16) __nv_bfloat16 g_ycat[(size_t)TT*BB*KC3];
__device__ __align__(16) __nv_bfloat16 g_w0cat[(size_t)G4*KC3];
__device__ __align__(16) __nv_bfloat16 g_w1cat[(size_t)G4*KC3];
__device__ __align__(16) __nv_bfloat16 g_R0h[(size_t)G4*HH];       // pair-reordered
__device__ __align__(16) __nv_bfloat16 g_R0l[(size_t)G4*HH];
__device__ __align__(16) __nv_bfloat16 g_R1h[(size_t)G4*HH];
__device__ __align__(16) __nv_bfloat16 g_R1l[(size_t)G4*HH];

// sync state (zero-init; replay-safe: monotonic flags + sense barrier)
__device__ unsigned g_barcnt;
__device__ unsigned g_barsense;
__device__ unsigned g_pflag[64];
__device__ __align__(16) float g_partial[64 * 2048];

// ---------------------------------------------------------------------------
// PTX helpers (family-generic legal)
// ---------------------------------------------------------------------------
__device__ __forceinline__ uint32_t s2u(const void* p) {
    uint32_t a;
    asm("{ .reg .u64 t; cvta.to.shared.u64 t, %1; cvt.u32.u64 %0, t; }" : "=r"(a) : "l"(p));
    return a;
}
__device__ __forceinline__ void cp16(uint32_t saddr, const void* g) {
    asm volatile("cp.async.cg.shared.global [%0], [%1], 16;" :: "r"(saddr), "l"(g));
}
#define CP_COMMIT() asm volatile("cp.async.commit_group;" ::: "memory")
#define CP_WAIT1()  asm volatile("cp.async.wait_group 1;" ::: "memory")

__device__ __forceinline__ void ldsm_x4(uint32_t* r, uint32_t addr) {
    asm volatile("ldmatrix.sync.aligned.m8n8.x4.shared.b16 {%0,%1,%2,%3}, [%4];"
        : "=r"(r[0]), "=r"(r[1]), "=r"(r[2]), "=r"(r[3]) : "r"(addr));
}
__device__ __forceinline__ void ldsm_x2(uint32_t* r, uint32_t addr) {
    asm volatile("ldmatrix.sync.aligned.m8n8.x2.shared.b16 {%0,%1}, [%2];"
        : "=r"(r[0]), "=r"(r[1]) : "r"(addr));
}
__device__ __forceinline__ void mma16816(float* d, const uint32_t* a, const uint32_t* b) {
    asm volatile("mma.sync.aligned.m16n8k16.row.col.f32.bf16.bf16.f32 "
        "{%0,%1,%2,%3}, {%4,%5,%6,%7}, {%8,%9}, {%0,%1,%2,%3};"
        : "+f"(d[0]), "+f"(d[1]), "+f"(d[2]), "+f"(d[3])
        : "r"(a[0]), "r"(a[1]), "r"(a[2]), "r"(a[3]), "r"(b[0]), "r"(b[1]));
}
__device__ __forceinline__ uint4 ldg_cg(const void* p) {
    uint4 v;
    asm volatile("ld.global.cg.v4.u32 {%0,%1,%2,%3}, [%4];"
        : "=r"(v.x), "=r"(v.y), "=r"(v.z), "=r"(v.w) : "l"(p));
    return v;
}
__device__ __forceinline__ float4 ldg_cg_f4(const void* p) {
    float4 v;
    asm volatile("ld.global.cg.v4.f32 {%0,%1,%2,%3}, [%4];"
        : "=f"(v.x), "=f"(v.y), "=f"(v.z), "=f"(v.w) : "l"(p));
    return v;
}
// Grid-wide sense-reversal barrier (called by thread 0 of each of 128 blocks)
__device__ __forceinline__ void grid_bar(unsigned& s) {
    s ^= 1u;
    __threadfence();
    if (atomicAdd(&g_barcnt, 1u) == 127u) {
        atomicExch(&g_barcnt, 0u);
        __threadfence();
        atomicExch(&g_barsense, s);
    } else {
        while (*(volatile unsigned*)&g_barsense != s) {}
    }
    __threadfence();
}

// ---------------------------------------------------------------------------
// Conversions
// ---------------------------------------------------------------------------
__global__ void split_cat(const float* __restrict__ src, __nv_bfloat16* __restrict__ dst,
                          size_t rows, int modeB) {
    size_t n = rows * HH;
    for (size_t i = (size_t)blockIdx.x * blockDim.x + threadIdx.x; i < n;
         i += (size_t)gridDim.x * blockDim.x) {
        size_t r = i >> 10; int k = (int)(i & 1023);
        float v = src[i];
        __nv_bfloat16 h = __float2bfloat16(v);
        __nv_bfloat16 l = __float2bfloat16(v - __bfloat162float(h));
        __nv_bfloat16* d = dst + r * KC3 + k;
        d[0] = h;
        d[1024] = modeB ? l : h;
        d[2048] = modeB ? h : l;
    }
}

// Pair reorder + split: dst row d = p*64 + gate*16 + hl ; src row = gate*1024 + p*16 + hl
__global__ void split_R(const float* __restrict__ R, __nv_bfloat16* __restrict__ hi,
                        __nv_bfloat16* __restrict__ lo) {
    size_t n = (size_t)G4 * HH;
    for (size_t i = (size_t)blockIdx.x * blockDim.x + threadIdx.x; i < n;
         i += (size_t)gridDim.x * blockDim.x) {
        int d = (int)(i >> 10), k = (int)(i & 1023);
        int p = d >> 6, gate = (d >> 4) & 3, hl = d & 15;
        int srow = gate * HH + p * 16 + hl;
        float v = R[(size_t)srow * HH + k];
        __nv_bfloat16 h = __float2bfloat16(v);
        hi[i] = h;
        lo[i] = __float2bfloat16(v - __bfloat162float(h));
    }
}

__global__ void split_h0(const float* __restrict__ src, __nv_bfloat16* __restrict__ yh,
                         __nv_bfloat16* __restrict__ yl) {
    int i = blockIdx.x * blockDim.x + threadIdx.x;
    if (i < BH) {
        float v = src[i];
        __nv_bfloat16 h = __float2bfloat16(v);
        yh[i] = h;
        yl[i] = __float2bfloat16(v - __bfloat162float(h));
    }
}

// ---------------------------------------------------------------------------
// Big GEMM: out[M][4096] = A[M][3072] @ B[4096][3072]^T + bias (unchanged, works)
// ---------------------------------------------------------------------------
#define GEMM_SMEM 40960

__device__ __forceinline__ void gemm_prefetch(uint32_t sb, int s,
    const __nv_bfloat16* __restrict__ A, const __nv_bfloat16* __restrict__ B,
    int m0, int n0, int k0, int tid)
{
    #pragma unroll
    for (int u = 0; u < 2; u++) {
        int unit = u * 256 + tid;
        int r = unit >> 2, c = unit & 3;
        cp16(sb + s * 20480 + r * 80 + c * 16, A + (size_t)(m0 + r) * KC3 + k0 + c * 8);
        cp16(sb + s * 20480 + 10240 + r * 80 + c * 16, B + (size_t)(n0 + r) * KC3 + k0 + c * 8);
    }
}

__global__ __launch_bounds__(256) void gemm_cat(
    const __nv_bfloat16* __restrict__ A, const __nv_bfloat16* __restrict__ B,
    const float* __restrict__ bW, const float* __restrict__ bR,
    float* __restrict__ out)
{
    extern __shared__ char smem[];
    const uint32_t sb = s2u(smem);
    const int tid = threadIdx.x, lane = tid & 31, w = tid >> 5;
    const int wm = w & 3, wn = w >> 2;
    const int m0 = blockIdx.y * 128, n0 = blockIdx.x * 128;

    float acc[2][8][4];
    #pragma unroll
    for (int i = 0; i < 2; i++)
        #pragma unroll
        for (int j = 0; j < 8; j++)
            #pragma unroll
            for (int q = 0; q < 4; q++) acc[i][j][q] = 0.f;

    gemm_prefetch(sb, 0, A, B, m0, n0, 0, tid); CP_COMMIT();
    gemm_prefetch(sb, 1, A, B, m0, n0, 32, tid); CP_COMMIT();

    for (int it = 0; it < 96; it++) {
        CP_WAIT1();
        __syncthreads();
        const int s = it & 1;
        const uint32_t ab = sb + s * 20480;
        const uint32_t bb = ab + 10240;
        #pragma unroll
        for (int kk = 0; kk < 2; kk++) {
            uint32_t af[2][4], bf[4][4];
            #pragma unroll
            for (int mh = 0; mh < 2; mh++) {
                int row = wm * 32 + mh * 16 + ((lane >> 3) & 1) * 8 + (lane & 7);
                int ch = kk * 2 + (lane >> 4);
                ldsm_x4(af[mh], ab + row * 80 + ch * 16);
            }
            #pragma unroll
            for (int p = 0; p < 4; p++) {
                int g = lane >> 3;
                int row = wn * 64 + p * 16 + (g >> 1) * 8 + (lane & 7);
                int ch = kk * 2 + (g & 1);
                ldsm_x4(bf[p], bb + row * 80 + ch * 16);
            }
            #pragma unroll
            for (int mh = 0; mh < 2; mh++)
                #pragma unroll
                for (int p = 0; p < 4; p++) {
                    mma16816(acc[mh][p * 2],     af[mh], &bf[p][0]);
                    mma16816(acc[mh][p * 2 + 1], af[mh], &bf[p][2]);
                }
        }
        __syncthreads();
        if (it + 2 < 96) gemm_prefetch(sb, s, A, B, m0, n0, (it + 2) * 32, tid);
        CP_COMMIT();
    }

    #pragma unroll
    for (int mh = 0; mh < 2; mh++)
        #pragma unroll
        for (int nj = 0; nj < 8; nj++) {
            int row = m0 + wm * 32 + mh * 16 + (lane >> 2);
            int col = n0 + wn * 64 + nj * 8 + 2 * (lane & 3);
            float b0 = bW[col] + bR[col];
            float b1 = bW[col + 1] + bR[col + 1];
            float2 v0 = make_float2(acc[mh][nj][0] + b0, acc[mh][nj][1] + b1);
            float2 v1 = make_float2(acc[mh][nj][2] + b0, acc[mh][nj][3] + b1);
            *reinterpret_cast<float2*>(out + (size_t)row * G4 + col) = v0;
            *reinterpret_cast<float2*>(out + (size_t)(row + 8) * G4 + col) = v1;
        }
}

// ---------------------------------------------------------------------------
// Persistent recurrence: 128 blocks x 256 threads; pair p = blk>>1, khalf = blk&1.
// Block owns R rows [p*64, p*64+64) x K-half [kh*512, +512), SMEM-resident (hi+lo).
// Per step: load y-half, 3-term mma, cross-pair partial reduction, fused cell
// update by khalf=0 (c in registers), one grid barrier.
// smem: Rh 64K | Rl 64K | yh 32K | yl 32K | gs 64x33 f32
// ---------------------------------------------------------------------------
#define PS_RSH 0
#define PS_RSL 65536
#define PS_YSH 131072
#define PS_YSL 163840
#define PS_GS  196608
#define PS_SMEM (196608 + 8448)

__global__ __launch_bounds__(256) void lstm_persist(
    const float* __restrict__ gates,
    const __nv_bfloat16* __restrict__ Rh, const __nv_bfloat16* __restrict__ Rl,
    __nv_bfloat16* __restrict__ ybh, __nv_bfloat16* __restrict__ ybl,  // [2][BH]
    const float* __restrict__ c0p,
    float* __restrict__ yout, long ystride,
    __nv_bfloat16* __restrict__ ycat,
    float* __restrict__ cnp)
{
    extern __shared__ char smem[];
    const uint32_t sb = s2u(smem);
    const int tid = threadIdx.x, lane = tid & 31, w = tid >> 5;
    const int p = blockIdx.x >> 1, kh = blockIdx.x & 1;

    // replay-safe bases (read before barrier0, before any writer of this launch)
    unsigned sense = *(volatile unsigned*)&g_barsense;
    unsigned pbase = *(volatile unsigned*)&g_pflag[p];

    // pointwise cell assignment: thread -> (batch b_pw, 2 h cells)
    const int b_pw = tid >> 3, hl_pw = (tid & 7) * 2;
    const int h_pw = p * 16 + hl_pw;
    float2 creg = make_float2(0.f, 0.f);
    if (kh == 0) creg = *reinterpret_cast<const float2*>(c0p + b_pw * HH + h_pw);

    // Load resident R slice (64 rows x 512 K, hi+lo), 16B-chunk XOR swizzle
    {
        const __nv_bfloat16* srcs[2] = { Rh + (size_t)p * 64 * HH + kh * 512,
                                         Rl + (size_t)p * 64 * HH + kh * 512 };
        #pragma unroll
        for (int s = 0; s < 2; s++) {
            #pragma unroll
            for (int u = 0; u < 16; u++) {
                int unit = u * 256 + tid;        // 0..4095
                int r = unit >> 6, cc = unit & 63;
                uint4 v = *reinterpret_cast<const uint4*>(srcs[s] + (size_t)r * HH + cc * 8);
                *reinterpret_cast<uint4*>(smem + (s ? PS_RSL : PS_RSH)
                                          + r * 1024 + (cc ^ (r & 7)) * 16) = v;
            }
        }
    }
    __syncthreads();
    if (tid == 0) grid_bar(sense);   // barrier0: bases read, R staged everywhere
    __syncthreads();

    float* gs = reinterpret_cast<float*>(smem + PS_GS);

    for (int t = 0; t < TT; t++) {
        const int buf = t & 1;
        // prefetch gates_x + (hidden under y load & mma)
        float2 gi, gf, gg2, go;
        if (kh == 0) {
            const float* gx = gates + (size_t)t * BB * G4 + (size_t)b_pw * G4;
            gi  = *reinterpret_cast<const float2*>(gx + h_pw);
            gf  = *reinterpret_cast<const float2*>(gx + 1024 + h_pw);
            gg2 = *reinterpret_cast<const float2*>(gx + 2048 + h_pw);
            go  = *reinterpret_cast<const float2*>(gx + 3072 + h_pw);
        }
        // load y half (bypass L1: other SMs rewrote it last step)
        {
            const __nv_bfloat16* yh_g = ybh + (size_t)buf * BH + kh * 512;
            const __nv_bfloat16* yl_g = ybl + (size_t)buf * BH + kh * 512;
            #pragma unroll
            for (int u = 0; u < 8; u++) {
                int unit = u * 256 + tid;        // 0..2047
                int r = unit >> 6, cc = unit & 63;
                uint4 v = ldg_cg(yh_g + (size_t)r * HH + cc * 8);
                *reinterpret_cast<uint4*>(smem + PS_YSH + r * 1024 + (cc ^ (r & 7)) * 16) = v;
            }
            #pragma unroll
            for (int u = 0; u < 8; u++) {
                int unit = u * 256 + tid;
                int r = unit >> 6, cc = unit & 63;
                uint4 v = ldg_cg(yl_g + (size_t)r * HH + cc * 8);
                *reinterpret_cast<uint4*>(smem + PS_YSL + r * 1024 + (cc ^ (r & 7)) * 16) = v;
            }
        }
        __syncthreads();

        float acc[2][4] = {{0.f,0.f,0.f,0.f},{0.f,0.f,0.f,0.f}};
        #pragma unroll 8
        for (int kk = 0; kk < 32; kk++) {
            uint32_t ah[2][4], al[2][4], bh2[2], bl2[2];
            #pragma unroll
            for (int mh = 0; mh < 2; mh++) {
                int row = mh * 16 + ((lane >> 3) & 1) * 8 + (lane & 7);
                int ch = (kk * 2 + (lane >> 4)) ^ (row & 7);
                ldsm_x4(ah[mh], sb + PS_YSH + row * 1024 + ch * 16);
                ldsm_x4(al[mh], sb + PS_YSL + row * 1024 + ch * 16);
            }
            {
                int r = w * 8 + (lane & 7);
                int ch = (kk * 2 + ((lane >> 3) & 1)) ^ (r & 7);
                ldsm_x2(bh2, sb + PS_RSH + r * 1024 + ch * 16);
                ldsm_x2(bl2, sb + PS_RSL + r * 1024 + ch * 16);
            }
            #pragma unroll
            for (int mh = 0; mh < 2; mh++) {
                mma16816(acc[mh], ah[mh], bh2);
                mma16816(acc[mh], ah[mh], bl2);
                mma16816(acc[mh], al[mh], bh2);
            }
        }

        if (kh == 1) {
            // publish partial, release flag
            float* dst = g_partial + p * 2048 + tid * 8;
            *reinterpret_cast<float4*>(dst)     = make_float4(acc[0][0], acc[0][1], acc[0][2], acc[0][3]);
            *reinterpret_cast<float4*>(dst + 4) = make_float4(acc[1][0], acc[1][1], acc[1][2], acc[1][3]);
            __threadfence();
            __syncthreads();
            if (tid == 0) atomicExch(&g_pflag[p], pbase + (unsigned)t + 1u);
        } else {
            if (tid == 0) {
                while (*(volatile unsigned*)&g_pflag[p] < pbase + (unsigned)t + 1u) {}
            }
            __syncthreads();
            __threadfence();
            const float* src = g_partial + p * 2048 + tid * 8;
            float4 pa = ldg_cg_f4(src);
            float4 pb = ldg_cg_f4(src + 4);
            acc[0][0] += pa.x; acc[0][1] += pa.y; acc[0][2] += pa.z; acc[0][3] += pa.w;
            acc[1][0] += pb.x; acc[1][1] += pb.y; acc[1][2] += pb.z; acc[1][3] += pb.w;
            // stage D[b][col] to smem exchange
            #pragma unroll
            for (int mh = 0; mh < 2; mh++) {
                int b0 = mh * 16 + (lane >> 2);
                int cc = w * 8 + (lane & 3) * 2;
                gs[cc * 33 + b0]           = acc[mh][0];
                gs[(cc + 1) * 33 + b0]     = acc[mh][1];
                gs[cc * 33 + b0 + 8]       = acc[mh][2];
                gs[(cc + 1) * 33 + b0 + 8] = acc[mh][3];
            }
            __syncthreads();
            // fused cell update for 2 cells (b_pw, hl_pw / hl_pw+1)
            float vi0 = gi.x + gs[(0  + hl_pw) * 33 + b_pw];
            float vi1 = gi.y + gs[(1  + hl_pw) * 33 + b_pw];
            float vf0 = gf.x + gs[(16 + hl_pw) * 33 + b_pw];
            float vf1 = gf.y + gs[(17 + hl_pw) * 33 + b_pw];
            float vg0 = gg2.x + gs[(32 + hl_pw) * 33 + b_pw];
            float vg1 = gg2.y + gs[(33 + hl_pw) * 33 + b_pw];
            float vo0 = go.x + gs[(48 + hl_pw) * 33 + b_pw];
            float vo1 = go.y + gs[(49 + hl_pw) * 33 + b_pw];
            float i0 = 1.f / (1.f + __expf(-vi0)), i1 = 1.f / (1.f + __expf(-vi1));
            float f0 = 1.f / (1.f + __expf(-vf0)), f1 = 1.f / (1.f + __expf(-vf1));
            float z0 = tanhf(vg0), z1 = tanhf(vg1);
            float o0 = 1.f / (1.f + __expf(-vo0)), o1 = 1.f / (1.f + __expf(-vo1));
            creg.x = f0 * creg.x + i0 * z0;
            creg.y = f1 * creg.y + i1 * z1;
            float y0 = o0 * tanhf(creg.x);
            float y1 = o1 * tanhf(creg.y);
            // outputs
            *reinterpret_cast<float2*>(yout + (size_t)t * ystride + b_pw * HH + h_pw)
                = make_float2(y0, y1);
            __nv_bfloat16 yh0 = __float2bfloat16(y0), yh1 = __float2bfloat16(y1);
            __nv_bfloat16 yl0 = __float2bfloat16(y0 - __bfloat162float(yh0));
            __nv_bfloat16 yl1 = __float2bfloat16(y1 - __bfloat162float(yh1));
            const int nbuf = (t + 1) & 1;
            __nv_bfloat162 hh; hh.x = yh0; hh.y = yh1;
            __nv_bfloat162 ll; ll.x = yl0; ll.y = yl1;
            *reinterpret_cast<__nv_bfloat162*>(ybh + (size_t)nbuf * BH + b_pw * HH + h_pw) = hh;
            *reinterpret_cast<__nv_bfloat162*>(ybl + (size_t)nbuf * BH + b_pw * HH + h_pw) = ll;
            if (ycat) {
                __nv_bfloat16* d = ycat + (size_t)t * BB * KC3 + (size_t)b_pw * KC3 + h_pw;
                *reinterpret_cast<__nv_bfloat162*>(d)        = hh;
                *reinterpret_cast<__nv_bfloat162*>(d + 1024) = hh;
                *reinterpret_cast<__nv_bfloat162*>(d + 2048) = ll;
            }
            if (t == TT - 1)
                *reinterpret_cast<float2*>(cnp + b_pw * HH + h_pw) = creg;
        }
        __syncthreads();
        if (tid == 0) grid_bar(sense);
        __syncthreads();
    }
}

// ---------------------------------------------------------------------------
extern "C" void kernel_launch(void* const* d_in, const int* in_sizes, int n_in,
                              void* d_out, int out_size)
{
    const float* x   = (const float*)d_in[0];
    const float* h0  = (const float*)d_in[1];
    const float* c0  = (const float*)d_in[2];
    const float* W0  = (const float*)d_in[3];
    const float* R0  = (const float*)d_in[4];
    const float* bW0 = (const float*)d_in[5];
    const float* bR0 = (const float*)d_in[6];
    const float* W1  = (const float*)d_in[7];
    const float* R1  = (const float*)d_in[8];
    const float* bW1 = (const float*)d_in[9];
    const float* bR1 = (const float*)d_in[10];

    float* y2 = (float*)d_out;
    float* hn = y2 + (size_t)TT * BH;
    float* cn = hn + 2 * BH;

    float *gates, *yf;
    __nv_bfloat16 *ybh, *ybl, *xcat, *ycat, *w0c, *w1c, *R0h, *R0l, *R1h, *R1l;
    cudaGetSymbolAddress((void**)&gates, g_gates);
    cudaGetSymbolAddress((void**)&yf,    g_yf);
    cudaGetSymbolAddress((void**)&ybh,   g_ybh);
    cudaGetSymbolAddress((void**)&ybl,   g_ybl);
    cudaGetSymbolAddress((void**)&xcat,  g_xcat);
    cudaGetSymbolAddress((void**)&ycat,  g_ycat);
    cudaGetSymbolAddress((void**)&w0c,   g_w0cat);
    cudaGetSymbolAddress((void**)&w1c,   g_w1cat);
    cudaGetSymbolAddress((void**)&R0h,   g_R0h);
    cudaGetSymbolAddress((void**)&R0l,   g_R0l);
    cudaGetSymbolAddress((void**)&R1h,   g_R1h);
    cudaGetSymbolAddress((void**)&R1l,   g_R1l);

    cudaFuncSetAttribute(gemm_cat, cudaFuncAttributeMaxDynamicSharedMemorySize, GEMM_SMEM);
    cudaFuncSetAttribute(lstm_persist, cudaFuncAttributeMaxDynamicSharedMemorySize, PS_SMEM);

    const size_t bhBytes = (size_t)BH * sizeof(float);
    const dim3 ggrid(G4 / 128, (TT * BB) / 128);

    // ---- conversions ----
    split_cat<<<2048, 256>>>(x, xcat, (size_t)TT * BB, 0);
    split_cat<<<2048, 256>>>(W0, w0c, (size_t)G4, 1);
    split_cat<<<2048, 256>>>(W1, w1c, (size_t)G4, 1);
    split_R<<<2048, 256>>>(R0, R0h, R0l);
    split_R<<<2048, 256>>>(R1, R1h, R1l);

    // ---- layer 0 ----
    gemm_cat<<<ggrid, 256, GEMM_SMEM>>>(xcat, w0c, bW0, bR0, gates);
    split_h0<<<BH / 256, 256>>>(h0, ybh, ybl);          // into buffer 0
    lstm_persist<<<128, 256, PS_SMEM>>>(gates, R0h, R0l, ybh, ybl,
                                        c0, yf, 0, ycat, cn);
    cudaMemcpyAsync(hn, yf, bhBytes, cudaMemcpyDeviceToDevice);

    // ---- layer 1 ----
    gemm_cat<<<ggrid, 256, GEMM_SMEM>>>(ycat, w1c, bW1, bR1, gates);
    split_h0<<<BH / 256, 256>>>(h0 + BH, ybh, ybl);     // into buffer 0
    lstm_persist<<<128, 256, PS_SMEM>>>(gates, R1h, R1l, ybh, ybl,
                                        c0 + BH, y2, BH, (__nv_bfloat16*)nullptr, cn + BH);
    cudaMemcpyAsync(hn + BH, y2 + (size_t)(TT - 1) * BH, bhBytes, cudaMemcpyDeviceToDevice);
}